// round 5
// baseline (speedup 1.0000x reference)
#include <cuda_runtime.h>
#include <cuda_bf16.h>
#include <cstdint>

// ---------------- problem constants ----------------
#define Nn 4096
#define Mm 4096
#define Dd 1024

// ---------------- GEMM tiling (int8) ----------------
#define BM 128
#define BN 128
#define BK 128                     // k bytes per stage (128 int8)
#define SKEW 16
#define BKP (BK + SKEW)            // 144 B rows; ldmatrix conflict-free
#define KT (Dd / BK)               // 8 iterations
#define NSPLIT 32
#define STAGES 3

#define A_SZ (BM * BKP)            // 18432 B
#define B_SZ (BN * BKP)            // 18432 B
#define STG (A_SZ + B_SZ)          // 36864 B
#define DYN_SMEM (STAGES * STG)    // 110592 B

// ---------------- scratch ----------------
__device__ __align__(256) unsigned char g_zq[Nn * Dd];   // z int8
__device__ __align__(256) unsigned char g_eq[Mm * Dd];   // e int8
__device__ __align__(256) float g_sz[Nn];                // z row scales
__device__ __align__(256) float g_se[Mm];                // e row scales
__device__ __align__(256) float g_zsq[Nn];               // exact fp32 ||z||^2
__device__ __align__(256) float g_esq[Mm];               // exact fp32 ||e||^2
__device__ __align__(256) unsigned g_partial[NSPLIT * Mm]; // packed (valbits|col)
__device__ __align__(256) float g_rdist[Mm];             // exact reranked min dist

// ---------------- PTX helpers ----------------
__device__ __forceinline__ void cp_async16(uint32_t saddr, const void* gptr) {
    asm volatile("cp.async.cg.shared.global [%0], [%1], 16;\n" ::"r"(saddr), "l"(gptr));
}
__device__ __forceinline__ void cp_commit() { asm volatile("cp.async.commit_group;\n"); }
template <int NW>
__device__ __forceinline__ void cp_wait() { asm volatile("cp.async.wait_group %0;\n" ::"n"(NW)); }

__device__ __forceinline__ void ldsm4(uint32_t& r0, uint32_t& r1, uint32_t& r2, uint32_t& r3,
                                      uint32_t saddr) {
    asm volatile("ldmatrix.sync.aligned.m8n8.x4.shared.b16 {%0,%1,%2,%3}, [%4];\n"
                 : "=r"(r0), "=r"(r1), "=r"(r2), "=r"(r3)
                 : "r"(saddr));
}
__device__ __forceinline__ void imma16832(int* c, const uint32_t* a, uint32_t b0, uint32_t b1) {
    asm volatile(
        "mma.sync.aligned.m16n8k32.row.col.s32.s8.s8.s32 "
        "{%0,%1,%2,%3}, {%4,%5,%6,%7}, {%8,%9}, {%0,%1,%2,%3};\n"
        : "+r"(c[0]), "+r"(c[1]), "+r"(c[2]), "+r"(c[3])
        : "r"(a[0]), "r"(a[1]), "r"(a[2]), "r"(a[3]), "r"(b0), "r"(b1));
}

// ================= kernel 1: quantize + exact squared norms (warp-per-row) =========
__global__ void __launch_bounds__(256) convert_kernel(const float* __restrict__ z,
                                                      const float* __restrict__ e) {
    const int gwarp = (blockIdx.x * 256 + threadIdx.x) >> 5;
    const int lane = threadIdx.x & 31;
    const float* src;
    unsigned char* dst;
    float *sqo, *sco;
    if (gwarp < Nn) {
        src = z + (size_t)gwarp * Dd;
        dst = g_zq + (size_t)gwarp * Dd;
        sqo = g_zsq + gwarp;
        sco = g_sz + gwarp;
    } else {
        const int r = gwarp - Nn;
        src = e + (size_t)r * Dd;
        dst = g_eq + (size_t)r * Dd;
        sqo = g_esq + r;
        sco = g_se + r;
    }
    const float4* s4 = reinterpret_cast<const float4*>(src);
    float4 v[8];
    float s = 0.f, am = 0.f;
#pragma unroll
    for (int i = 0; i < 8; i++) {
        v[i] = s4[lane + 32 * i];
        s += v[i].x * v[i].x + v[i].y * v[i].y + v[i].z * v[i].z + v[i].w * v[i].w;
        am = fmaxf(am, fmaxf(fmaxf(fabsf(v[i].x), fabsf(v[i].y)),
                             fmaxf(fabsf(v[i].z), fabsf(v[i].w))));
    }
#pragma unroll
    for (int o = 16; o; o >>= 1) {
        s += __shfl_xor_sync(0xffffffffu, s, o);
        am = fmaxf(am, __shfl_xor_sync(0xffffffffu, am, o));
    }
    const float inv = 127.f / am;
    unsigned* d32 = reinterpret_cast<unsigned*>(dst);
#pragma unroll
    for (int i = 0; i < 8; i++) {
        const int a0 = __float2int_rn(fminf(fmaxf(v[i].x * inv, -127.f), 127.f));
        const int a1 = __float2int_rn(fminf(fmaxf(v[i].y * inv, -127.f), 127.f));
        const int a2 = __float2int_rn(fminf(fmaxf(v[i].z * inv, -127.f), 127.f));
        const int a3 = __float2int_rn(fminf(fmaxf(v[i].w * inv, -127.f), 127.f));
        const unsigned p = (unsigned)(a0 & 0xFF) | ((unsigned)(a1 & 0xFF) << 8) |
                           ((unsigned)(a2 & 0xFF) << 16) | ((unsigned)(a3 & 0xFF) << 24);
        d32[lane + 32 * i] = p;
    }
    if (lane == 0) {
        *sqo = s;
        *sco = am / 127.f;
    }
}

// ================= kernel 2: int8 IMMA GEMM + fused row-argmin =================
// CTA: 128 e-rows x 128 z-cols, full K=1024. 8 warps (4m x 2n), warp tile 32x64.
// 3-stage cp.async, one __syncthreads per BK=128-byte tile. Epilogue tracks argmin
// via packed (float-bits | 12-bit col) unsigned min.
__global__ void __launch_bounds__(256, 2) gemm_min_kernel() {
    extern __shared__ char dyn_raw[];
    __shared__ unsigned srm[2][BM];

    const uint32_t smem = (uint32_t)__cvta_generic_to_shared(dyn_raw);

    const int tid = threadIdx.x;
    const int lane = tid & 31;
    const int warp = tid >> 5;
    const int wm = warp >> 1;        // 0..3 : 32-row group
    const int wn = warp & 1;         // 0..1 : 64-col group

    const int m0 = blockIdx.x * BM;
    const int split = blockIdx.y;
    const int n0 = split * BN;

    // cp.async: 128 rows, 2 threads/row, each thread 4 consecutive 16B chunks (64B)
    const int lrow = tid >> 1;
    const int lseg = (tid & 1) * 4;

    // ldmatrix lane mapping (byte addressed)
    const int ldrow = lane & 15;
    const int ldcol = (lane >> 4) * 16;

    int acc[2][8][4];
#pragma unroll
    for (int mi = 0; mi < 2; mi++)
#pragma unroll
        for (int g = 0; g < 8; g++)
#pragma unroll
            for (int q = 0; q < 4; q++) acc[mi][g][q] = 0;

    auto issue = [&](int j, int slot) {
        const int k0 = j * BK;
        const uint32_t sa = smem + slot * STG;
        const uint32_t sb = sa + A_SZ;
        const unsigned char* gA = g_eq + (size_t)(m0 + lrow) * Dd + k0 + lseg * 16;
        const unsigned char* gB = g_zq + (size_t)(n0 + lrow) * Dd + k0 + lseg * 16;
        const uint32_t dA = sa + (uint32_t)(lrow * BKP + lseg * 16);
        const uint32_t dB = sb + (uint32_t)(lrow * BKP + lseg * 16);
#pragma unroll
        for (int c = 0; c < 4; c++) {
            cp_async16(dA + c * 16, gA + c * 16);
            cp_async16(dB + c * 16, gB + c * 16);
        }
    };

    issue(0, 0);
    cp_commit();
    issue(1, 1);
    cp_commit();

    int cslot = 0, islot = 2;
    for (int j = 0; j < KT; j++) {
        cp_wait<1>();
        __syncthreads();

        if (j + 2 < KT) issue(j + 2, islot);
        cp_commit();
        if (++islot == STAGES) islot = 0;

        const uint32_t sa = smem + cslot * STG;
        const uint32_t sb = sa + A_SZ;
        if (++cslot == STAGES) cslot = 0;

#pragma unroll
        for (int ks = 0; ks < BK; ks += 32) {
            uint32_t a[2][4];
#pragma unroll
            for (int mi = 0; mi < 2; mi++) {
                const uint32_t addr =
                    sa + (uint32_t)((wm * 32 + mi * 16 + ldrow) * BKP + ks + ldcol);
                ldsm4(a[mi][0], a[mi][1], a[mi][2], a[mi][3], addr);
            }
#pragma unroll
            for (int g = 0; g < 4; g++) {
                uint32_t b0, b1, b2, b3;
                const uint32_t addr =
                    sb + (uint32_t)((wn * 64 + g * 16 + ldrow) * BKP + ks + ldcol);
                ldsm4(b0, b1, b2, b3, addr);
#pragma unroll
                for (int mi = 0; mi < 2; mi++) {
                    imma16832(acc[mi][2 * g], a[mi], b0, b2);
                    imma16832(acc[mi][2 * g + 1], a[mi], b1, b3);
                }
            }
        }
    }

    // ---- epilogue: approx dist (value-only for selection) + argmin packing ----
    const int r = lane >> 2;
    const float se0 = g_se[m0 + wm * 32 + r];
    const float se1 = g_se[m0 + wm * 32 + r + 8];
    const float se2 = g_se[m0 + wm * 32 + 16 + r];
    const float se3 = g_se[m0 + wm * 32 + 24 + r];

    unsigned rk0 = 0xFFFFFFFFu, rk1 = 0xFFFFFFFFu, rk2 = 0xFFFFFFFFu, rk3 = 0xFFFFFFFFu;
    const int colbase = n0 + wn * 64 + (lane & 3) * 2;
#pragma unroll
    for (int g = 0; g < 8; g++) {
        const int col = colbase + g * 8;
        const float2 zs = *reinterpret_cast<const float2*>(g_zsq + col);
        const float2 sz = *reinterpret_cast<const float2*>(g_sz + col);
        const float wx0 = -2.f * sz.x, wx1 = -2.f * sz.y;

        auto fold = [&](float se, int q0, int q1, int mi, unsigned& rk) {
            const float v0 = fmaf(wx0 * se, (float)acc[mi][g][q0], zs.x);
            const float v1 = fmaf(wx1 * se, (float)acc[mi][g][q1], zs.y);
            const unsigned k0 = (__float_as_uint(v0) & 0xFFFFF000u) | (unsigned)col;
            const unsigned k1 = (__float_as_uint(v1) & 0xFFFFF000u) | (unsigned)(col + 1);
            rk = min(rk, min(k0, k1));
        };
        fold(se0, 0, 1, 0, rk0);
        fold(se1, 2, 3, 0, rk1);
        fold(se2, 0, 1, 1, rk2);
        fold(se3, 2, 3, 1, rk3);
    }

#pragma unroll
    for (int off = 1; off <= 2; off <<= 1) {
        rk0 = min(rk0, __shfl_xor_sync(0xffffffffu, rk0, off));
        rk1 = min(rk1, __shfl_xor_sync(0xffffffffu, rk1, off));
        rk2 = min(rk2, __shfl_xor_sync(0xffffffffu, rk2, off));
        rk3 = min(rk3, __shfl_xor_sync(0xffffffffu, rk3, off));
    }
    if ((lane & 3) == 0) {
        srm[wn][wm * 32 + r] = rk0;
        srm[wn][wm * 32 + r + 8] = rk1;
        srm[wn][wm * 32 + 16 + r] = rk2;
        srm[wn][wm * 32 + 24 + r] = rk3;
    }
    __syncthreads();
    if (tid < BM) {
        g_partial[split * Mm + m0 + tid] = min(srm[0][tid], srm[1][tid]);
    }
}

// ================= kernel 3: rerank — exact fp32 distance at the argmin ============
__global__ void __launch_bounds__(256) rerank_kernel(const float* __restrict__ z,
                                                     const float* __restrict__ e) {
    const int m = (blockIdx.x * 256 + threadIdx.x) >> 5;  // one warp per code
    const int lane = threadIdx.x & 31;

    // min over the 32 splits (one per lane), keep packed key
    unsigned k = g_partial[lane * Mm + m];
#pragma unroll
    for (int o = 16; o; o >>= 1) k = min(k, __shfl_xor_sync(0xffffffffu, k, o));
    const int col = (int)(k & 0xFFFu);

    const float4* zp = reinterpret_cast<const float4*>(z + (size_t)col * Dd);
    const float4* ep = reinterpret_cast<const float4*>(e + (size_t)m * Dd);
    float dot = 0.f;
#pragma unroll
    for (int i = 0; i < 8; i++) {
        const float4 a = zp[lane + 32 * i];
        const float4 b = ep[lane + 32 * i];
        dot += a.x * b.x + a.y * b.y + a.z * b.z + a.w * b.w;
    }
#pragma unroll
    for (int o = 16; o; o >>= 1) dot += __shfl_xor_sync(0xffffffffu, dot, o);
    if (lane == 0) {
        g_rdist[m] = g_zsq[col] + g_esq[m] - 2.f * dot;
    }
}

// ================= kernel 4: finalize (mean) =================
__global__ void finalize_kernel(float* __restrict__ out) {
    const int t = threadIdx.x;  // 256
    float s = 0.f;
    for (int m = t; m < Mm; m += 256) s += g_rdist[m];
#pragma unroll
    for (int off = 16; off; off >>= 1) s += __shfl_xor_sync(0xffffffffu, s, off);
    __shared__ float ws[8];
    if ((t & 31) == 0) ws[t >> 5] = s;
    __syncthreads();
    if (t == 0) {
        float tot = 0.f;
#pragma unroll
        for (int i = 0; i < 8; i++) tot += ws[i];
        out[0] = tot / (float)Mm;
    }
}

// ================= entry point =================
extern "C" void kernel_launch(void* const* d_in, const int* in_sizes, int n_in,
                              void* d_out, int out_size) {
    const float* z = (const float*)d_in[0];  // [4096, 1024]
    const float* e = (const float*)d_in[1];  // [4096, 1024]
    float* out = (float*)d_out;              // [1]

    convert_kernel<<<(Nn + Mm) / 8, 256>>>(z, e);

    static bool attr_set = false;
    if (!attr_set) {
        cudaFuncSetAttribute(gemm_min_kernel, cudaFuncAttributeMaxDynamicSharedMemorySize,
                             DYN_SMEM);
        attr_set = true;
    }
    dim3 grid(Mm / BM, NSPLIT);  // 32 x 32 = 1024 CTAs
    gemm_min_kernel<<<grid, 256, DYN_SMEM>>>();

    rerank_kernel<<<Mm / 8, 256>>>(z, e);
    finalize_kernel<<<1, 256>>>(out);
}

// round 6
// speedup vs baseline: 1.4905x; 1.4905x over previous
#include <cuda_runtime.h>
#include <cuda_bf16.h>
#include <cstdint>

// ---------------- problem constants ----------------
#define Nn 4096
#define Mm 4096
#define Dd 1024

// ---------------- GEMM tiling ----------------
#define BM 128
#define BN 64
#define BK 64
#define SKEW 8
#define BKP (BK + SKEW)            // 72 bf16 = 144B rows; ldmatrix conflict-free
#define KT (Dd / BK)               // 16 iterations per CTA
#define NSPLIT (Nn / BN)           // 64 n-splits
#define STAGES 3

#define A_SZ (BM * BKP * 2)        // 18432 B
#define B_SZ (BN * BKP * 2)        // 9216 B
#define STG (A_SZ + B_SZ)          // 27648 B
#define DYN_SMEM (STAGES * STG)    // 82944 B (x2 CTA/SM = 166 KB)

// ---------------- scratch ----------------
__device__ __align__(256) __nv_bfloat16 g_zb[Nn * Dd];
__device__ __align__(256) __nv_bfloat16 g_eb[Mm * Dd];
__device__ __align__(256) float g_zsq[Nn];
__device__ __align__(256) float g_esq[Mm];
__device__ __align__(256) float g_partial[NSPLIT * Mm];
__device__ __align__(256) float g_bsum[16];

// ---------------- PTX helpers ----------------
__device__ __forceinline__ void cp_async16(uint32_t saddr, const void* gptr) {
    asm volatile("cp.async.cg.shared.global [%0], [%1], 16;\n" ::"r"(saddr), "l"(gptr));
}
__device__ __forceinline__ void cp_commit() { asm volatile("cp.async.commit_group;\n"); }
template <int NW>
__device__ __forceinline__ void cp_wait() { asm volatile("cp.async.wait_group %0;\n" ::"n"(NW)); }

__device__ __forceinline__ void ldsm4(uint32_t& r0, uint32_t& r1, uint32_t& r2, uint32_t& r3,
                                      uint32_t saddr) {
    asm volatile("ldmatrix.sync.aligned.m8n8.x4.shared.b16 {%0,%1,%2,%3}, [%4];\n"
                 : "=r"(r0), "=r"(r1), "=r"(r2), "=r"(r3)
                 : "r"(saddr));
}
__device__ __forceinline__ void mma16816(float* c, const uint32_t* a, uint32_t b0, uint32_t b1) {
    asm volatile(
        "mma.sync.aligned.m16n8k16.row.col.f32.bf16.bf16.f32 "
        "{%0,%1,%2,%3}, {%4,%5,%6,%7}, {%8,%9}, {%0,%1,%2,%3};\n"
        : "+f"(c[0]), "+f"(c[1]), "+f"(c[2]), "+f"(c[3])
        : "r"(a[0]), "r"(a[1]), "r"(a[2]), "r"(a[3]), "r"(b0), "r"(b1));
}

// ================= kernel 1: convert + squared norms (warp-per-row) =================
__global__ void __launch_bounds__(256) convert_kernel(const float* __restrict__ z,
                                                      const float* __restrict__ e) {
    const int gwarp = (blockIdx.x * 256 + threadIdx.x) >> 5;
    const int lane = threadIdx.x & 31;
    const float* src;
    __nv_bfloat16* dst;
    float* sqo;
    if (gwarp < Nn) {
        src = z + (size_t)gwarp * Dd;
        dst = g_zb + (size_t)gwarp * Dd;
        sqo = g_zsq + gwarp;
    } else {
        const int r = gwarp - Nn;
        src = e + (size_t)r * Dd;
        dst = g_eb + (size_t)r * Dd;
        sqo = g_esq + r;
    }
    float s = 0.f;
    const float4* s4 = reinterpret_cast<const float4*>(src);
    uint4* d4 = reinterpret_cast<uint4*>(dst);
#pragma unroll
    for (int i = 0; i < 4; i++) {
        const int idx = lane + 32 * i;
        float4 v0 = s4[2 * idx];
        float4 v1 = s4[2 * idx + 1];
        __nv_bfloat162 p0 = __floats2bfloat162_rn(v0.x, v0.y);
        __nv_bfloat162 p1 = __floats2bfloat162_rn(v0.z, v0.w);
        __nv_bfloat162 p2 = __floats2bfloat162_rn(v1.x, v1.y);
        __nv_bfloat162 p3 = __floats2bfloat162_rn(v1.z, v1.w);
        uint4 w;
        w.x = *reinterpret_cast<unsigned*>(&p0);
        w.y = *reinterpret_cast<unsigned*>(&p1);
        w.z = *reinterpret_cast<unsigned*>(&p2);
        w.w = *reinterpret_cast<unsigned*>(&p3);
        d4[idx] = w;
        s += v0.x * v0.x + v0.y * v0.y + v0.z * v0.z + v0.w * v0.w;
        s += v1.x * v1.x + v1.y * v1.y + v1.z * v1.z + v1.w * v1.w;
    }
#pragma unroll
    for (int o = 16; o; o >>= 1) s += __shfl_xor_sync(0xffffffffu, s, o);
    if (lane == 0) *sqo = s;
}

// ================= kernel 2: mma.sync GEMM + fused row-min =================
// CTA: 128 e-rows x 64 z-cols, full K=1024. 8 warps (4m x 2n), warp tile 32x32.
// 3-stage cp.async pipeline, one __syncthreads per BK=64 tile. 2048 CTAs -> ~99% packing.
__global__ void __launch_bounds__(256, 2) gemm_min_kernel() {
    extern __shared__ char dyn_raw[];
    __shared__ float srm[2][BM];

    const uint32_t smem = (uint32_t)__cvta_generic_to_shared(dyn_raw);

    const int tid = threadIdx.x;
    const int lane = tid & 31;
    const int warp = tid >> 5;
    const int wm = warp >> 1;        // 0..3 : 32-row group
    const int wn = warp & 1;         // 0..1 : 32-col group

    const int m0 = blockIdx.x * BM;
    const int split = blockIdx.y;
    const int n0 = split * BN;

    // cp.async: A 128 rows, 2 threads/row, 64B each; B 64 rows, 4 threads/row, 32B each
    const int arow = tid >> 1;
    const int aseg = (tid & 1) * 4;          // 16B-chunk base
    const int brow = tid >> 2;
    const int bseg = (tid & 3) * 2;

    // ldmatrix lane mapping
    const int ldrow = lane & 15;
    const int ldcol = (lane >> 4) * 8;

    float acc[2][4][4];
#pragma unroll
    for (int mi = 0; mi < 2; mi++)
#pragma unroll
        for (int g = 0; g < 4; g++)
#pragma unroll
            for (int q = 0; q < 4; q++) acc[mi][g][q] = 0.f;

    auto issue = [&](int j, int slot) {
        const int k0 = j * BK;
        const uint32_t sa = smem + slot * STG;
        const uint32_t sb = sa + A_SZ;
        {
            const __nv_bfloat16* g = g_eb + (size_t)(m0 + arow) * Dd + k0 + aseg * 8;
            const uint32_t d = sa + (uint32_t)(arow * BKP + aseg * 8) * 2;
#pragma unroll
            for (int c = 0; c < 4; c++) cp_async16(d + c * 16, g + c * 8);
        }
        {
            const __nv_bfloat16* g = g_zb + (size_t)(n0 + brow) * Dd + k0 + bseg * 8;
            const uint32_t d = sb + (uint32_t)(brow * BKP + bseg * 8) * 2;
#pragma unroll
            for (int c = 0; c < 2; c++) cp_async16(d + c * 16, g + c * 8);
        }
    };

    issue(0, 0);
    cp_commit();
    issue(1, 1);
    cp_commit();

    int cslot = 0, islot = 2;
    for (int j = 0; j < KT; j++) {
        cp_wait<1>();
        __syncthreads();

        if (j + 2 < KT) issue(j + 2, islot);
        cp_commit();
        if (++islot == STAGES) islot = 0;

        const uint32_t sa = smem + cslot * STG;
        const uint32_t sb = sa + A_SZ;
        if (++cslot == STAGES) cslot = 0;

#pragma unroll
        for (int ks = 0; ks < BK; ks += 16) {
            uint32_t a[2][4];
#pragma unroll
            for (int mi = 0; mi < 2; mi++) {
                const uint32_t addr =
                    sa + (uint32_t)((wm * 32 + mi * 16 + ldrow) * BKP + ks + ldcol) * 2;
                ldsm4(a[mi][0], a[mi][1], a[mi][2], a[mi][3], addr);
            }
#pragma unroll
            for (int g = 0; g < 2; g++) {
                uint32_t b0, b1, b2, b3;
                const uint32_t addr =
                    sb + (uint32_t)((wn * 32 + g * 16 + ldrow) * BKP + ks + ldcol) * 2;
                ldsm4(b0, b1, b2, b3, addr);
#pragma unroll
                for (int mi = 0; mi < 2; mi++) {
                    mma16816(acc[mi][2 * g], a[mi], b0, b2);
                    mma16816(acc[mi][2 * g + 1], a[mi], b1, b3);
                }
            }
        }
    }

    // ---- epilogue: v = zsq[n] - 2*acc ; per-row min ----
    const float INF = __int_as_float(0x7f800000);
    float rm0 = INF, rm1 = INF, rm2 = INF, rm3 = INF;
    const int colbase = n0 + wn * 32 + (lane & 3) * 2;
#pragma unroll
    for (int g = 0; g < 4; g++) {
        const int col = colbase + g * 8;
        const float zs0 = g_zsq[col];
        const float zs1 = g_zsq[col + 1];
        {
            const float v0 = fminf(fmaf(-2.f, acc[0][g][0], zs0), fmaf(-2.f, acc[0][g][1], zs1));
            const float v1 = fminf(fmaf(-2.f, acc[0][g][2], zs0), fmaf(-2.f, acc[0][g][3], zs1));
            rm0 = fminf(rm0, v0);
            rm1 = fminf(rm1, v1);
        }
        {
            const float v0 = fminf(fmaf(-2.f, acc[1][g][0], zs0), fmaf(-2.f, acc[1][g][1], zs1));
            const float v1 = fminf(fmaf(-2.f, acc[1][g][2], zs0), fmaf(-2.f, acc[1][g][3], zs1));
            rm2 = fminf(rm2, v0);
            rm3 = fminf(rm3, v1);
        }
    }

#pragma unroll
    for (int off = 1; off <= 2; off <<= 1) {
        rm0 = fminf(rm0, __shfl_xor_sync(0xffffffffu, rm0, off));
        rm1 = fminf(rm1, __shfl_xor_sync(0xffffffffu, rm1, off));
        rm2 = fminf(rm2, __shfl_xor_sync(0xffffffffu, rm2, off));
        rm3 = fminf(rm3, __shfl_xor_sync(0xffffffffu, rm3, off));
    }
    if ((lane & 3) == 0) {
        const int r = lane >> 2;
        srm[wn][wm * 32 + r] = rm0;
        srm[wn][wm * 32 + r + 8] = rm1;
        srm[wn][wm * 32 + 16 + r] = rm2;
        srm[wn][wm * 32 + 24 + r] = rm3;
    }
    __syncthreads();
    if (tid < BM) {
        g_partial[split * Mm + m0 + tid] = fminf(srm[0][tid], srm[1][tid]);
    }
}

// ================= kernel 3: per-row min over splits + block sums =================
__global__ void __launch_bounds__(256) rowsum_kernel() {
    const int m = blockIdx.x * 256 + threadIdx.x;  // 16 blocks x 256 = 4096
    float mn = g_partial[m];
#pragma unroll 8
    for (int sp = 1; sp < NSPLIT; sp++) mn = fminf(mn, g_partial[sp * Mm + m]);
    float s = mn + g_esq[m];
#pragma unroll
    for (int o = 16; o; o >>= 1) s += __shfl_xor_sync(0xffffffffu, s, o);
    __shared__ float ws[8];
    if ((threadIdx.x & 31) == 0) ws[threadIdx.x >> 5] = s;
    __syncthreads();
    if (threadIdx.x == 0) {
        float tot = 0.f;
#pragma unroll
        for (int i = 0; i < 8; i++) tot += ws[i];
        g_bsum[blockIdx.x] = tot;
    }
}

// ================= kernel 4: finalize (1 warp) =================
__global__ void finalize_kernel(float* __restrict__ out) {
    const int lane = threadIdx.x;
    float s = (lane < 16) ? g_bsum[lane] : 0.f;
#pragma unroll
    for (int o = 16; o; o >>= 1) s += __shfl_xor_sync(0xffffffffu, s, o);
    if (lane == 0) out[0] = s / (float)Mm;
}

// ================= entry point =================
extern "C" void kernel_launch(void* const* d_in, const int* in_sizes, int n_in,
                              void* d_out, int out_size) {
    const float* z = (const float*)d_in[0];  // [4096, 1024]
    const float* e = (const float*)d_in[1];  // [4096, 1024]
    float* out = (float*)d_out;              // [1]

    convert_kernel<<<(Nn + Mm) / 8, 256>>>(z, e);

    static bool attr_set = false;
    if (!attr_set) {
        cudaFuncSetAttribute(gemm_min_kernel, cudaFuncAttributeMaxDynamicSharedMemorySize,
                             DYN_SMEM);
        attr_set = true;
    }
    dim3 grid(Mm / BM, NSPLIT);  // 32 x 64 = 2048 CTAs -> 6.92 waves @ 2 CTA/SM
    gemm_min_kernel<<<grid, 256, DYN_SMEM>>>();

    rowsum_kernel<<<16, 256>>>();
    finalize_kernel<<<1, 32>>>(out);
}

// round 7
// speedup vs baseline: 1.7298x; 1.1605x over previous
#include <cuda_runtime.h>
#include <cuda_bf16.h>
#include <cstdint>

// ---------------- problem constants ----------------
#define Nn 4096
#define Mm 4096
#define Dd 1024

// ---------------- GEMM tiling (round-4 proven shape) ----------------
#define BM 128
#define BN 128
#define BK 64
#define SKEW 8
#define BKP (BK + SKEW)            // 72 bf16 = 144B rows; ldmatrix conflict-free
#define KT (Dd / BK)               // 16 iterations per CTA
#define NSPLIT 32
#define STAGES 3

#define A_SZ (BM * BKP * 2)        // 18432 B
#define B_SZ (BN * BKP * 2)        // 18432 B
#define STG (A_SZ + B_SZ)          // 36864 B
#define DYN_SMEM (STAGES * STG)    // 110592 B (x2 CTA/SM = 221 KB <= 227)

#define GRID_TILES (Mm / BM * NSPLIT)   // 1024 CTAs

// ---------------- scratch ----------------
__device__ __align__(256) __nv_bfloat16 g_zb[Nn * Dd];
__device__ __align__(256) __nv_bfloat16 g_eb[Mm * Dd];
__device__ __align__(256) float g_zsq[Nn];
__device__ __align__(256) float g_esq[Mm];
__device__ __align__(256) unsigned g_rowmin[Mm];   // full-distance bits (positive float)
__device__ unsigned g_done;

// ---------------- PTX helpers ----------------
__device__ __forceinline__ void cp_async16(uint32_t saddr, const void* gptr) {
    asm volatile("cp.async.cg.shared.global [%0], [%1], 16;\n" ::"r"(saddr), "l"(gptr));
}
__device__ __forceinline__ void cp_commit() { asm volatile("cp.async.commit_group;\n"); }
template <int NW>
__device__ __forceinline__ void cp_wait() { asm volatile("cp.async.wait_group %0;\n" ::"n"(NW)); }

__device__ __forceinline__ void ldsm4(uint32_t* r, uint32_t saddr) {
    asm volatile("ldmatrix.sync.aligned.m8n8.x4.shared.b16 {%0,%1,%2,%3}, [%4];\n"
                 : "=r"(r[0]), "=r"(r[1]), "=r"(r[2]), "=r"(r[3])
                 : "r"(saddr));
}
__device__ __forceinline__ void mma16816(float* c, const uint32_t* a, uint32_t b0, uint32_t b1) {
    asm volatile(
        "mma.sync.aligned.m16n8k16.row.col.f32.bf16.bf16.f32 "
        "{%0,%1,%2,%3}, {%4,%5,%6,%7}, {%8,%9}, {%0,%1,%2,%3};\n"
        : "+f"(c[0]), "+f"(c[1]), "+f"(c[2]), "+f"(c[3])
        : "r"(a[0]), "r"(a[1]), "r"(a[2]), "r"(a[3]), "r"(b0), "r"(b1));
}

// ================= kernel 1: convert + squared norms + result-buffer init ==========
__global__ void __launch_bounds__(256) convert_kernel(const float* __restrict__ z,
                                                      const float* __restrict__ e) {
    if (blockIdx.x == 0) {
        // init fused-reduction state (every call: graph-replay safe)
#pragma unroll
        for (int i = 0; i < Mm / 256; i++) g_rowmin[threadIdx.x + 256 * i] = 0x7f800000u;
        if (threadIdx.x == 0) g_done = 0u;
    }
    const int gwarp = (blockIdx.x * 256 + threadIdx.x) >> 5;
    const int lane = threadIdx.x & 31;
    const float* src;
    __nv_bfloat16* dst;
    float* sqo;
    if (gwarp < Nn) {
        src = z + (size_t)gwarp * Dd;
        dst = g_zb + (size_t)gwarp * Dd;
        sqo = g_zsq + gwarp;
    } else {
        const int r = gwarp - Nn;
        src = e + (size_t)r * Dd;
        dst = g_eb + (size_t)r * Dd;
        sqo = g_esq + r;
    }
    float s = 0.f;
    const float4* s4 = reinterpret_cast<const float4*>(src);
    uint4* d4 = reinterpret_cast<uint4*>(dst);
#pragma unroll
    for (int i = 0; i < 4; i++) {
        const int idx = lane + 32 * i;
        float4 v0 = s4[2 * idx];
        float4 v1 = s4[2 * idx + 1];
        __nv_bfloat162 p0 = __floats2bfloat162_rn(v0.x, v0.y);
        __nv_bfloat162 p1 = __floats2bfloat162_rn(v0.z, v0.w);
        __nv_bfloat162 p2 = __floats2bfloat162_rn(v1.x, v1.y);
        __nv_bfloat162 p3 = __floats2bfloat162_rn(v1.z, v1.w);
        uint4 w;
        w.x = *reinterpret_cast<unsigned*>(&p0);
        w.y = *reinterpret_cast<unsigned*>(&p1);
        w.z = *reinterpret_cast<unsigned*>(&p2);
        w.w = *reinterpret_cast<unsigned*>(&p3);
        d4[idx] = w;
        s += v0.x * v0.x + v0.y * v0.y + v0.z * v0.z + v0.w * v0.w;
        s += v1.x * v1.x + v1.y * v1.y + v1.z * v1.z + v1.w * v1.w;
    }
#pragma unroll
    for (int o = 16; o; o >>= 1) s += __shfl_xor_sync(0xffffffffu, s, o);
    if (lane == 0) *sqo = s;
}

// ================= kernel 2: GEMM + row-min + fused final reduction =================
// CTA: 128 e-rows x 128 z-cols, K=1024. 8 warps (4m x 2n), warp tile 32x64.
// 3-stage cp.async, register double-buffered fragments, atomicMin epilogue,
// last CTA performs the global sum + mean.
__global__ void __launch_bounds__(256, 2) gemm_min_kernel(float* __restrict__ out) {
    extern __shared__ char dyn_raw[];
    __shared__ float srm[2][BM];
    __shared__ float ws[8];

    const uint32_t smem = (uint32_t)__cvta_generic_to_shared(dyn_raw);

    const int tid = threadIdx.x;
    const int lane = tid & 31;
    const int warp = tid >> 5;
    const int wm = warp >> 1;        // 0..3 : 32-row group
    const int wn = warp & 1;         // 0..1 : 64-col group

    const int m0 = blockIdx.x * BM;
    const int n0 = blockIdx.y * BN;

    // cp.async: 128 rows, 2 threads/row, each thread 4 consecutive 16B chunks
    const int lrow = tid >> 1;
    const int lseg = (tid & 1) * 4;

    // ldmatrix lane mapping
    const int ldrow = lane & 15;
    const int ldcol = (lane >> 4) * 8;

    float acc[2][8][4];
#pragma unroll
    for (int mi = 0; mi < 2; mi++)
#pragma unroll
        for (int g = 0; g < 8; g++)
#pragma unroll
            for (int q = 0; q < 4; q++) acc[mi][g][q] = 0.f;

    auto issue = [&](int j, int slot) {
        const int k0 = j * BK;
        const uint32_t sa = smem + slot * STG;
        const uint32_t sb = sa + A_SZ;
        const __nv_bfloat16* gA = g_eb + (size_t)(m0 + lrow) * Dd + k0 + lseg * 8;
        const __nv_bfloat16* gB = g_zb + (size_t)(n0 + lrow) * Dd + k0 + lseg * 8;
        const uint32_t dA = sa + (uint32_t)(lrow * BKP + lseg * 8) * 2;
        const uint32_t dB = sb + (uint32_t)(lrow * BKP + lseg * 8) * 2;
#pragma unroll
        for (int c = 0; c < 4; c++) {
            cp_async16(dA + c * 16, gA + c * 8);
            cp_async16(dB + c * 16, gB + c * 8);
        }
    };

    issue(0, 0);
    cp_commit();
    issue(1, 1);
    cp_commit();

    uint32_t fa[2][2][4];   // [buf][mi][frag]
    uint32_t fb[2][4][4];   // [buf][g][frag]

    int cslot = 0, islot = 2;
    for (int j = 0; j < KT; j++) {
        cp_wait<1>();
        __syncthreads();

        if (j + 2 < KT) issue(j + 2, islot);
        cp_commit();
        if (++islot == STAGES) islot = 0;

        const uint32_t sa = smem + cslot * STG;
        const uint32_t sb = sa + A_SZ;
        if (++cslot == STAGES) cslot = 0;

        auto load_fa = [&](int ks, uint32_t (*dst)[4]) {
#pragma unroll
            for (int mi = 0; mi < 2; mi++)
                ldsm4(dst[mi],
                      sa + (uint32_t)((wm * 32 + mi * 16 + ldrow) * BKP + ks * 16 + ldcol) * 2);
        };
        auto load_fb = [&](int ks, uint32_t (*dst)[4]) {
#pragma unroll
            for (int g = 0; g < 4; g++)
                ldsm4(dst[g],
                      sb + (uint32_t)((wn * 64 + g * 16 + ldrow) * BKP + ks * 16 + ldcol) * 2);
        };

        load_fa(0, fa[0]);
        load_fb(0, fb[0]);
#pragma unroll
        for (int ks = 0; ks < 4; ks++) {
            const int cur = ks & 1;
            if (ks < 3) {               // prefetch next step's fragments
                load_fa(ks + 1, fa[cur ^ 1]);
                load_fb(ks + 1, fb[cur ^ 1]);
            }
#pragma unroll
            for (int g = 0; g < 4; g++) {
#pragma unroll
                for (int mi = 0; mi < 2; mi++) {
                    mma16816(acc[mi][2 * g], fa[cur][mi], fb[cur][g][0], fb[cur][g][2]);
                    mma16816(acc[mi][2 * g + 1], fa[cur][mi], fb[cur][g][1], fb[cur][g][3]);
                }
            }
        }
    }

    // ---- epilogue: v = zsq[n] - 2*acc ; per-row min ----
    const float INF = __int_as_float(0x7f800000);
    float rm0 = INF, rm1 = INF, rm2 = INF, rm3 = INF;
    const int colbase = n0 + wn * 64 + (lane & 3) * 2;
#pragma unroll
    for (int g = 0; g < 8; g++) {
        const int col = colbase + g * 8;
        const float zs0 = g_zsq[col];
        const float zs1 = g_zsq[col + 1];
        {
            const float v0 = fminf(fmaf(-2.f, acc[0][g][0], zs0), fmaf(-2.f, acc[0][g][1], zs1));
            const float v1 = fminf(fmaf(-2.f, acc[0][g][2], zs0), fmaf(-2.f, acc[0][g][3], zs1));
            rm0 = fminf(rm0, v0);
            rm1 = fminf(rm1, v1);
        }
        {
            const float v0 = fminf(fmaf(-2.f, acc[1][g][0], zs0), fmaf(-2.f, acc[1][g][1], zs1));
            const float v1 = fminf(fmaf(-2.f, acc[1][g][2], zs0), fmaf(-2.f, acc[1][g][3], zs1));
            rm2 = fminf(rm2, v0);
            rm3 = fminf(rm3, v1);
        }
    }

#pragma unroll
    for (int off = 1; off <= 2; off <<= 1) {
        rm0 = fminf(rm0, __shfl_xor_sync(0xffffffffu, rm0, off));
        rm1 = fminf(rm1, __shfl_xor_sync(0xffffffffu, rm1, off));
        rm2 = fminf(rm2, __shfl_xor_sync(0xffffffffu, rm2, off));
        rm3 = fminf(rm3, __shfl_xor_sync(0xffffffffu, rm3, off));
    }
    if ((lane & 3) == 0) {
        const int r = lane >> 2;
        srm[wn][wm * 32 + r] = rm0;
        srm[wn][wm * 32 + r + 8] = rm1;
        srm[wn][wm * 32 + 16 + r] = rm2;
        srm[wn][wm * 32 + 24 + r] = rm3;
    }
    __syncthreads();
    if (tid < BM) {
        // full distance (add exact ||e||^2): positive -> float bits unsigned-monotone
        const float v = fminf(srm[0][tid], srm[1][tid]) + g_esq[m0 + tid];
        atomicMin(&g_rowmin[m0 + tid], __float_as_uint(v));
    }

    // ---- last-CTA fused final reduction ----
    __shared__ unsigned s_last;
    __threadfence();
    __syncthreads();
    if (tid == 0) s_last = atomicAdd(&g_done, 1u);
    __syncthreads();
    if (s_last == GRID_TILES - 1) {
        __threadfence();
        float s = 0.f;
#pragma unroll
        for (int i = 0; i < Mm / 256; i++)
            s += __uint_as_float(g_rowmin[tid + 256 * i]);
#pragma unroll
        for (int o = 16; o; o >>= 1) s += __shfl_xor_sync(0xffffffffu, s, o);
        if ((tid & 31) == 0) ws[tid >> 5] = s;
        __syncthreads();
        if (tid == 0) {
            float tot = 0.f;
#pragma unroll
            for (int i = 0; i < 8; i++) tot += ws[i];
            out[0] = tot / (float)Mm;
        }
    }
}

// ================= entry point =================
extern "C" void kernel_launch(void* const* d_in, const int* in_sizes, int n_in,
                              void* d_out, int out_size) {
    const float* z = (const float*)d_in[0];  // [4096, 1024]
    const float* e = (const float*)d_in[1];  // [4096, 1024]
    float* out = (float*)d_out;              // [1]

    convert_kernel<<<(Nn + Mm) / 8, 256>>>(z, e);

    static bool attr_set = false;
    if (!attr_set) {
        cudaFuncSetAttribute(gemm_min_kernel, cudaFuncAttributeMaxDynamicSharedMemorySize,
                             DYN_SMEM);
        attr_set = true;
    }
    dim3 grid(Mm / BM, NSPLIT);  // 32 x 32 = 1024 CTAs
    gemm_min_kernel<<<grid, 256, DYN_SMEM>>>(out);
}

// round 8
// speedup vs baseline: 2.1458x; 1.2405x over previous
#include <cuda_runtime.h>
#include <cuda_bf16.h>
#include <cstdint>

// ---------------- problem constants ----------------
#define Nn 4096
#define Mm 4096
#define Dd 1024

// ---------------- GEMM tiling ----------------
#define BM 128
#define BN 128
#define BK 64
#define SKEW 8
#define BKP (BK + SKEW)            // 72 bf16 = 144B rows; ldmatrix conflict-free
#define KT (Dd / BK)               // 16 iterations per CTA
#define NSPLIT 32
#define STAGES 3
#define THREADS 512                // 16 warps: 4m x 4n grid of 32x32 warp tiles

#define A_SZ (BM * BKP * 2)        // 18432 B
#define B_SZ (BN * BKP * 2)        // 18432 B
#define STG (A_SZ + B_SZ)          // 36864 B
#define DYN_SMEM (STAGES * STG)    // 110592 B (x2 CTA/SM = 221 KB)

#define GRID_TILES (Mm / BM * NSPLIT)   // 1024 CTAs

// ---------------- scratch ----------------
__device__ __align__(256) __nv_bfloat16 g_zb[Nn * Dd];
__device__ __align__(256) __nv_bfloat16 g_eb[Mm * Dd];
__device__ __align__(256) float g_zsq[Nn];
__device__ __align__(256) float g_esq[Mm];
__device__ __align__(256) unsigned g_rowmin[Mm];   // full-distance bits (positive float)
__device__ unsigned g_done;

// ---------------- PTX helpers ----------------
__device__ __forceinline__ void cp_async16(uint32_t saddr, const void* gptr) {
    asm volatile("cp.async.cg.shared.global [%0], [%1], 16;\n" ::"r"(saddr), "l"(gptr));
}
__device__ __forceinline__ void cp_commit() { asm volatile("cp.async.commit_group;\n"); }
template <int NW>
__device__ __forceinline__ void cp_wait() { asm volatile("cp.async.wait_group %0;\n" ::"n"(NW)); }

__device__ __forceinline__ void ldsm4(uint32_t* r, uint32_t saddr) {
    asm volatile("ldmatrix.sync.aligned.m8n8.x4.shared.b16 {%0,%1,%2,%3}, [%4];\n"
                 : "=r"(r[0]), "=r"(r[1]), "=r"(r[2]), "=r"(r[3])
                 : "r"(saddr));
}
__device__ __forceinline__ void mma16816(float* c, const uint32_t* a, uint32_t b0, uint32_t b1) {
    asm volatile(
        "mma.sync.aligned.m16n8k16.row.col.f32.bf16.bf16.f32 "
        "{%0,%1,%2,%3}, {%4,%5,%6,%7}, {%8,%9}, {%0,%1,%2,%3};\n"
        : "+f"(c[0]), "+f"(c[1]), "+f"(c[2]), "+f"(c[3])
        : "r"(a[0]), "r"(a[1]), "r"(a[2]), "r"(a[3]), "r"(b0), "r"(b1));
}

// ================= kernel 1: convert + squared norms + result-buffer init ==========
__global__ void __launch_bounds__(256) convert_kernel(const float* __restrict__ z,
                                                      const float* __restrict__ e) {
    if (blockIdx.x == 0) {
#pragma unroll
        for (int i = 0; i < Mm / 256; i++) g_rowmin[threadIdx.x + 256 * i] = 0x7f800000u;
        if (threadIdx.x == 0) g_done = 0u;
    }
    const int gwarp = (blockIdx.x * 256 + threadIdx.x) >> 5;
    const int lane = threadIdx.x & 31;
    const float* src;
    __nv_bfloat16* dst;
    float* sqo;
    if (gwarp < Nn) {
        src = z + (size_t)gwarp * Dd;
        dst = g_zb + (size_t)gwarp * Dd;
        sqo = g_zsq + gwarp;
    } else {
        const int r = gwarp - Nn;
        src = e + (size_t)r * Dd;
        dst = g_eb + (size_t)r * Dd;
        sqo = g_esq + r;
    }
    float s = 0.f;
    const float4* s4 = reinterpret_cast<const float4*>(src);
    uint4* d4 = reinterpret_cast<uint4*>(dst);
#pragma unroll
    for (int i = 0; i < 4; i++) {
        const int idx = lane + 32 * i;
        float4 v0 = s4[2 * idx];
        float4 v1 = s4[2 * idx + 1];
        __nv_bfloat162 p0 = __floats2bfloat162_rn(v0.x, v0.y);
        __nv_bfloat162 p1 = __floats2bfloat162_rn(v0.z, v0.w);
        __nv_bfloat162 p2 = __floats2bfloat162_rn(v1.x, v1.y);
        __nv_bfloat162 p3 = __floats2bfloat162_rn(v1.z, v1.w);
        uint4 w;
        w.x = *reinterpret_cast<unsigned*>(&p0);
        w.y = *reinterpret_cast<unsigned*>(&p1);
        w.z = *reinterpret_cast<unsigned*>(&p2);
        w.w = *reinterpret_cast<unsigned*>(&p3);
        d4[idx] = w;
        s += v0.x * v0.x + v0.y * v0.y + v0.z * v0.z + v0.w * v0.w;
        s += v1.x * v1.x + v1.y * v1.y + v1.z * v1.z + v1.w * v1.w;
    }
#pragma unroll
    for (int o = 16; o; o >>= 1) s += __shfl_xor_sync(0xffffffffu, s, o);
    if (lane == 0) *sqo = s;
}

// ================= kernel 2: GEMM + row-min + fused final reduction =================
// CTA: 128x128 tile, K=1024. 16 warps (4m x 4n), warp tile 32x32, 2 CTA/SM ->
// 32 warps/SM. 3-stage cp.async, one sync per BK tile, atomicMin fused tail.
__global__ void __launch_bounds__(THREADS, 2) gemm_min_kernel(float* __restrict__ out) {
    extern __shared__ char dyn_raw[];
    __shared__ float srm[4][BM];
    __shared__ float ws[16];

    const uint32_t smem = (uint32_t)__cvta_generic_to_shared(dyn_raw);

    const int tid = threadIdx.x;
    const int lane = tid & 31;
    const int warp = tid >> 5;
    const int wm = warp >> 2;        // 0..3 : 32-row group
    const int wn = warp & 3;         // 0..3 : 32-col group

    const int m0 = blockIdx.x * BM;
    const int n0 = blockIdx.y * BN;

    // cp.async: 128 rows, 4 threads/row, each thread 2 consecutive 16B chunks (32B)
    const int lrow = tid >> 2;
    const int lseg = (tid & 3) * 2;

    // ldmatrix lane mapping
    const int ldrow = lane & 15;
    const int ldcol = (lane >> 4) * 8;

    float acc[2][4][4];
#pragma unroll
    for (int mi = 0; mi < 2; mi++)
#pragma unroll
        for (int g = 0; g < 4; g++)
#pragma unroll
            for (int q = 0; q < 4; q++) acc[mi][g][q] = 0.f;

    auto issue = [&](int j, int slot) {
        const int k0 = j * BK;
        const uint32_t sa = smem + slot * STG;
        const uint32_t sb = sa + A_SZ;
        const __nv_bfloat16* gA = g_eb + (size_t)(m0 + lrow) * Dd + k0 + lseg * 8;
        const __nv_bfloat16* gB = g_zb + (size_t)(n0 + lrow) * Dd + k0 + lseg * 8;
        const uint32_t dA = sa + (uint32_t)(lrow * BKP + lseg * 8) * 2;
        const uint32_t dB = sb + (uint32_t)(lrow * BKP + lseg * 8) * 2;
        cp_async16(dA, gA);
        cp_async16(dA + 16, gA + 8);
        cp_async16(dB, gB);
        cp_async16(dB + 16, gB + 8);
    };

    issue(0, 0);
    cp_commit();
    issue(1, 1);
    cp_commit();

    int cslot = 0, islot = 2;
    for (int j = 0; j < KT; j++) {
        cp_wait<1>();
        __syncthreads();

        if (j + 2 < KT) issue(j + 2, islot);
        cp_commit();
        if (++islot == STAGES) islot = 0;

        const uint32_t sa = smem + cslot * STG;
        const uint32_t sb = sa + A_SZ;
        if (++cslot == STAGES) cslot = 0;

#pragma unroll
        for (int ks = 0; ks < BK; ks += 16) {
            uint32_t a[2][4];
#pragma unroll
            for (int mi = 0; mi < 2; mi++)
                ldsm4(a[mi], sa + (uint32_t)((wm * 32 + mi * 16 + ldrow) * BKP + ks + ldcol) * 2);
            uint32_t b[2][4];
#pragma unroll
            for (int h = 0; h < 2; h++)
                ldsm4(b[h], sb + (uint32_t)((wn * 32 + h * 16 + ldrow) * BKP + ks + ldcol) * 2);
#pragma unroll
            for (int h = 0; h < 2; h++) {
#pragma unroll
                for (int mi = 0; mi < 2; mi++) {
                    mma16816(acc[mi][2 * h], a[mi], b[h][0], b[h][2]);
                    mma16816(acc[mi][2 * h + 1], a[mi], b[h][1], b[h][3]);
                }
            }
        }
    }

    // ---- epilogue: v = zsq[n] - 2*acc ; per-row min ----
    const float INF = __int_as_float(0x7f800000);
    float rm0 = INF, rm1 = INF, rm2 = INF, rm3 = INF;
    const int colbase = n0 + wn * 32 + (lane & 3) * 2;
#pragma unroll
    for (int g = 0; g < 4; g++) {
        const int col = colbase + g * 8;
        const float zs0 = g_zsq[col];
        const float zs1 = g_zsq[col + 1];
        {
            const float v0 = fminf(fmaf(-2.f, acc[0][g][0], zs0), fmaf(-2.f, acc[0][g][1], zs1));
            const float v1 = fminf(fmaf(-2.f, acc[0][g][2], zs0), fmaf(-2.f, acc[0][g][3], zs1));
            rm0 = fminf(rm0, v0);
            rm1 = fminf(rm1, v1);
        }
        {
            const float v0 = fminf(fmaf(-2.f, acc[1][g][0], zs0), fmaf(-2.f, acc[1][g][1], zs1));
            const float v1 = fminf(fmaf(-2.f, acc[1][g][2], zs0), fmaf(-2.f, acc[1][g][3], zs1));
            rm2 = fminf(rm2, v0);
            rm3 = fminf(rm3, v1);
        }
    }

#pragma unroll
    for (int off = 1; off <= 2; off <<= 1) {
        rm0 = fminf(rm0, __shfl_xor_sync(0xffffffffu, rm0, off));
        rm1 = fminf(rm1, __shfl_xor_sync(0xffffffffu, rm1, off));
        rm2 = fminf(rm2, __shfl_xor_sync(0xffffffffu, rm2, off));
        rm3 = fminf(rm3, __shfl_xor_sync(0xffffffffu, rm3, off));
    }
    // rows wm*32 + {r, r+8, 16+r, 24+r}; 4 warps (wn=0..3) per row group
    if ((lane & 3) == 0) {
        const int r = lane >> 2;
        srm[wn][wm * 32 + r] = rm0;
        srm[wn][wm * 32 + r + 8] = rm1;
        srm[wn][wm * 32 + 16 + r] = rm2;
        srm[wn][wm * 32 + 24 + r] = rm3;
    }
    __syncthreads();
    if (tid < BM) {
        const float v = fminf(fminf(srm[0][tid], srm[1][tid]),
                              fminf(srm[2][tid], srm[3][tid])) + g_esq[m0 + tid];
        atomicMin(&g_rowmin[m0 + tid], __float_as_uint(v));
    }

    // ---- last-CTA fused final reduction ----
    __shared__ unsigned s_last;
    __threadfence();
    __syncthreads();
    if (tid == 0) s_last = atomicAdd(&g_done, 1u);
    __syncthreads();
    if (s_last == GRID_TILES - 1) {
        __threadfence();
        float s = 0.f;
#pragma unroll
        for (int i = 0; i < Mm / THREADS; i++)
            s += __uint_as_float(g_rowmin[tid + THREADS * i]);
#pragma unroll
        for (int o = 16; o; o >>= 1) s += __shfl_xor_sync(0xffffffffu, s, o);
        if ((tid & 31) == 0) ws[tid >> 5] = s;
        __syncthreads();
        if (tid == 0) {
            float tot = 0.f;
#pragma unroll
            for (int i = 0; i < 16; i++) tot += ws[i];
            out[0] = tot / (float)Mm;
        }
    }
}

// ================= entry point =================
extern "C" void kernel_launch(void* const* d_in, const int* in_sizes, int n_in,
                              void* d_out, int out_size) {
    const float* z = (const float*)d_in[0];  // [4096, 1024]
    const float* e = (const float*)d_in[1];  // [4096, 1024]
    float* out = (float*)d_out;              // [1]

    convert_kernel<<<(Nn + Mm) / 8, 256>>>(z, e);

    static bool attr_set = false;
    if (!attr_set) {
        cudaFuncSetAttribute(gemm_min_kernel, cudaFuncAttributeMaxDynamicSharedMemorySize,
                             DYN_SMEM);
        attr_set = true;
    }
    dim3 grid(Mm / BM, NSPLIT);  // 32 x 32 = 1024 CTAs
    gemm_min_kernel<<<grid, THREADS, DYN_SMEM>>>(out);
}